// round 4
// baseline (speedup 1.0000x reference)
#include <cuda_runtime.h>
#include <cuda_bf16.h>
#include <cstddef>

// ---------------------------------------------------------------------------
// AttentionLePE: x[8,32,32,512] -> qkv GEMM -> 16-head attention (d=32)
//                + 5x5 depthwise conv (LePE) -> proj GEMM + bias
// Round 1: fp32 baseline. Scratch via __device__ globals (no allocs).
// ---------------------------------------------------------------------------

#define BATCH 8
#define HH 32
#define WW 32
#define DIM 512
#define NHEADS 16
#define HD 32
#define NTOK 1024              // HH*WW
#define M_ROWS (BATCH * NTOK)  // 8192
#define C3 (3 * DIM)           // 1536

__device__ float g_qkv[(size_t)M_ROWS * C3];   // 50.3 MB
__device__ float g_ao[(size_t)M_ROWS * DIM];   // 16.8 MB (attn out + lepe)

// ---------------------------------------------------------------------------
// TN SGEMM: C[m][n] = sum_k A[m*K+k] * B[n*K+k] (+ bias[n])
// BM=BN=128, BK=8, 256 threads, 8x8 per thread (2x2 of float4 tiles)
// ---------------------------------------------------------------------------
__global__ __launch_bounds__(256) void sgemm_tn(
    const float* __restrict__ A, const float* __restrict__ B,
    const float* __restrict__ bias, float* __restrict__ C,
    int M, int N, int K)
{
    __shared__ float As[8][128];
    __shared__ float Bs[8][128];

    const int tid = threadIdx.x;
    const int bm = blockIdx.y * 128;
    const int bn = blockIdx.x * 128;
    const int ty = tid >> 4;          // 0..15
    const int tx = tid & 15;          // 0..15

    // load mapping: each thread one float4 of A and one of B per BK step
    const int lr = tid >> 1;          // 0..127 (row within tile)
    const int lk = (tid & 1) << 2;    // 0 or 4 (k offset)

    const float* Ag = A + (size_t)(bm + lr) * K + lk;
    const float* Bg = B + (size_t)(bn + lr) * K + lk;

    float acc[8][8];
#pragma unroll
    for (int i = 0; i < 8; i++)
#pragma unroll
        for (int j = 0; j < 8; j++) acc[i][j] = 0.f;

    for (int k0 = 0; k0 < K; k0 += 8) {
        float4 av = *(const float4*)(Ag + k0);
        float4 bv = *(const float4*)(Bg + k0);
        __syncthreads();
        As[lk + 0][lr] = av.x; As[lk + 1][lr] = av.y;
        As[lk + 2][lr] = av.z; As[lk + 3][lr] = av.w;
        Bs[lk + 0][lr] = bv.x; Bs[lk + 1][lr] = bv.y;
        Bs[lk + 2][lr] = bv.z; Bs[lk + 3][lr] = bv.w;
        __syncthreads();

#pragma unroll
        for (int kk = 0; kk < 8; kk++) {
            float4 a0 = *(const float4*)&As[kk][ty * 4];
            float4 a1 = *(const float4*)&As[kk][64 + ty * 4];
            float4 b0 = *(const float4*)&Bs[kk][tx * 4];
            float4 b1 = *(const float4*)&Bs[kk][64 + tx * 4];
            float a[8] = {a0.x, a0.y, a0.z, a0.w, a1.x, a1.y, a1.z, a1.w};
            float b[8] = {b0.x, b0.y, b0.z, b0.w, b1.x, b1.y, b1.z, b1.w};
#pragma unroll
            for (int i = 0; i < 8; i++)
#pragma unroll
                for (int j = 0; j < 8; j++)
                    acc[i][j] = fmaf(a[i], b[j], acc[i][j]);
        }
    }

    // epilogue
    float bia0[4] = {0.f, 0.f, 0.f, 0.f}, bia1[4] = {0.f, 0.f, 0.f, 0.f};
    if (bias) {
#pragma unroll
        for (int j = 0; j < 4; j++) {
            bia0[j] = bias[bn + tx * 4 + j];
            bia1[j] = bias[bn + 64 + tx * 4 + j];
        }
    }
#pragma unroll
    for (int i = 0; i < 8; i++) {
        int row = bm + ((i < 4) ? (ty * 4 + i) : (64 + ty * 4 + (i - 4)));
        float4 c0 = make_float4(acc[i][0] + bia0[0], acc[i][1] + bia0[1],
                                acc[i][2] + bia0[2], acc[i][3] + bia0[3]);
        float4 c1 = make_float4(acc[i][4] + bia1[0], acc[i][5] + bia1[1],
                                acc[i][6] + bia1[2], acc[i][7] + bia1[3]);
        *(float4*)&C[(size_t)row * N + bn + tx * 4] = c0;
        *(float4*)&C[(size_t)row * N + bn + 64 + tx * 4] = c1;
    }
}

// ---------------------------------------------------------------------------
// Flash attention: one thread = one query row. d=32 in registers.
// grid (8 qtiles, 16 heads, 8 batch), block 128.
// ---------------------------------------------------------------------------
__global__ __launch_bounds__(128) void attn_kernel(float* __restrict__ out)
{
    const int b = blockIdx.z;
    const int h = blockIdx.y;
    const int t = threadIdx.x;
    const int n = blockIdx.x * 128 + t;
    const float scale = 0.17677669529663689f;  // 1/sqrt(32)

    __shared__ float Ks[32][32];
    __shared__ float Vs[32][32];

    const float* qkv = g_qkv;
    const size_t base = (size_t)b * NTOK * C3;

    float q[32], acc[32];
    {
        const float* qp = qkv + base + (size_t)n * C3 + h * HD;
#pragma unroll
        for (int i = 0; i < 8; i++) {
            float4 v = *(const float4*)(qp + i * 4);
            q[i * 4 + 0] = v.x; q[i * 4 + 1] = v.y;
            q[i * 4 + 2] = v.z; q[i * 4 + 3] = v.w;
        }
    }
#pragma unroll
    for (int i = 0; i < 32; i++) acc[i] = 0.f;

    float mrun = -1e30f, l = 0.f;

    for (int kt = 0; kt < 32; kt++) {
        __syncthreads();
        // load 32x32 K and V tiles (256 float4 each, 2 per thread)
#pragma unroll
        for (int i = 0; i < 2; i++) {
            int idx = t + i * 128;          // 0..255
            int r = idx >> 3;
            int c4 = (idx & 7) << 2;
            const float* kp = qkv + base + (size_t)(kt * 32 + r) * C3 + DIM + h * HD + c4;
            *(float4*)&Ks[r][c4] = *(const float4*)kp;
            *(float4*)&Vs[r][c4] = *(const float4*)(kp + DIM);
        }
        __syncthreads();

        float s[32];
        float tmax = -1e30f;
#pragma unroll
        for (int j = 0; j < 32; j++) {
            float sj = 0.f;
#pragma unroll
            for (int i = 0; i < 8; i++) {
                float4 k4 = *(const float4*)&Ks[j][i * 4];
                sj = fmaf(q[i * 4 + 0], k4.x, sj);
                sj = fmaf(q[i * 4 + 1], k4.y, sj);
                sj = fmaf(q[i * 4 + 2], k4.z, sj);
                sj = fmaf(q[i * 4 + 3], k4.w, sj);
            }
            sj *= scale;
            s[j] = sj;
            tmax = fmaxf(tmax, sj);
        }

        float mnew = fmaxf(mrun, tmax);
        float alpha = __expf(mrun - mnew);
        l *= alpha;
#pragma unroll
        for (int i = 0; i < 32; i++) acc[i] *= alpha;

#pragma unroll
        for (int j = 0; j < 32; j++) {
            float p = __expf(s[j] - mnew);
            l += p;
#pragma unroll
            for (int i = 0; i < 8; i++) {
                float4 v4 = *(const float4*)&Vs[j][i * 4];
                acc[i * 4 + 0] = fmaf(p, v4.x, acc[i * 4 + 0]);
                acc[i * 4 + 1] = fmaf(p, v4.y, acc[i * 4 + 1]);
                acc[i * 4 + 2] = fmaf(p, v4.z, acc[i * 4 + 2]);
                acc[i * 4 + 3] = fmaf(p, v4.w, acc[i * 4 + 3]);
            }
        }
        mrun = mnew;
    }

    float inv = 1.f / l;
    float* op = out + (size_t)(b * NTOK + n) * DIM + h * HD;
#pragma unroll
    for (int i = 0; i < 8; i++) {
        float4 v = make_float4(acc[i * 4 + 0] * inv, acc[i * 4 + 1] * inv,
                               acc[i * 4 + 2] * inv, acc[i * 4 + 3] * inv);
        *(float4*)(op + i * 4) = v;
    }
}

// ---------------------------------------------------------------------------
// LePE 5x5 depthwise conv, added into attention output.
// grid = 8192 pixels, block 512 channels.
// ---------------------------------------------------------------------------
__global__ __launch_bounds__(512) void lepe_kernel(
    const float* __restrict__ x, const float* __restrict__ w,
    const float* __restrict__ bias, float* __restrict__ out)
{
    const int c = threadIdx.x;
    const int pix = blockIdx.x;
    const int b = pix >> 10;
    const int y = (pix >> 5) & 31;
    const int xx = pix & 31;

    float wreg[25];
#pragma unroll
    for (int i = 0; i < 25; i++) wreg[i] = w[c * 25 + i];

    float acc = bias[c];
#pragma unroll
    for (int dy = 0; dy < 5; dy++) {
        int yy = y + dy - 2;
        if (yy < 0 || yy > 31) continue;
#pragma unroll
        for (int dx = 0; dx < 5; dx++) {
            int xs = xx + dx - 2;
            if (xs < 0 || xs > 31) continue;
            acc = fmaf(x[((size_t)((b * 32 + yy) * 32 + xs)) * DIM + c],
                       wreg[dy * 5 + dx], acc);
        }
    }
    out[(size_t)pix * DIM + c] += acc;
}

// ---------------------------------------------------------------------------
extern "C" void kernel_launch(void* const* d_in, const int* in_sizes, int n_in,
                              void* d_out, int out_size)
{
    const float* x      = (const float*)d_in[0];
    const float* w_qkv  = (const float*)d_in[1];
    const float* w_proj = (const float*)d_in[2];
    const float* b_proj = (const float*)d_in[3];
    const float* w_lepe = (const float*)d_in[4];
    const float* b_lepe = (const float*)d_in[5];
    float* out = (float*)d_out;

    float *qkv_ptr = nullptr, *ao_ptr = nullptr;
    cudaGetSymbolAddress((void**)&qkv_ptr, g_qkv);
    cudaGetSymbolAddress((void**)&ao_ptr, g_ao);

    // 1) qkv = x @ w_qkv^T   [8192,512] x [1536,512]^T
    {
        dim3 grid(C3 / 128, M_ROWS / 128);
        sgemm_tn<<<grid, 256>>>(x, w_qkv, nullptr, qkv_ptr, M_ROWS, C3, DIM);
    }
    // 2) attention -> g_ao
    {
        dim3 grid(NTOK / 128, NHEADS, BATCH);
        attn_kernel<<<grid, 128>>>(ao_ptr);
    }
    // 3) g_ao += lepe(x)
    {
        lepe_kernel<<<BATCH * HH * WW, DIM>>>(x, w_lepe, b_lepe, ao_ptr);
    }
    // 4) out = g_ao @ w_proj^T + b_proj
    {
        dim3 grid(DIM / 128, M_ROWS / 128);
        sgemm_tn<<<grid, 256>>>(ao_ptr, w_proj, b_proj, out, M_ROWS, DIM, DIM);
    }
}

// round 10
// speedup vs baseline: 1.3506x; 1.3506x over previous
#include <cuda_runtime.h>
#include <cuda_bf16.h>
#include <cstdint>
#include <cstddef>

// ---------------------------------------------------------------------------
// AttentionLePE: x[8,32,32,512] -> qkv GEMM -> 16-head attention (d=32)
//                + 5x5 depthwise conv (LePE) -> proj GEMM + bias
// Round 9: dense GEMMs on mma.sync tf32 (baseline PTX — the harness stages
// compute_103 PTX, which rejects tcgen05; HMMA is the available tensor path).
// Attention + lepe unchanged from the verified fp32 baseline.
// ---------------------------------------------------------------------------

#define BATCH 8
#define HH 32
#define WW 32
#define DIM 512
#define NHEADS 16
#define HD 32
#define NTOK 1024              // HH*WW
#define M_ROWS (BATCH * NTOK)  // 8192
#define C3 (3 * DIM)           // 1536

__device__ float g_qkv[(size_t)M_ROWS * C3];   // 50.3 MB
__device__ float g_ao[(size_t)M_ROWS * DIM];   // 16.8 MB (attn out + lepe)

__device__ __forceinline__ uint32_t cvt_tf32(float f) {
    uint32_t r;
    asm("cvt.rna.tf32.f32 %0, %1;" : "=r"(r) : "f"(f));
    return r;
}

__device__ __forceinline__ void mma_tf32(
    float c[4], uint32_t a0, uint32_t a1, uint32_t a2, uint32_t a3,
    uint32_t b0, uint32_t b1)
{
    asm volatile(
        "mma.sync.aligned.m16n8k8.row.col.f32.tf32.tf32.f32 "
        "{%0,%1,%2,%3}, {%4,%5,%6,%7}, {%8,%9}, {%0,%1,%2,%3};"
        : "+f"(c[0]), "+f"(c[1]), "+f"(c[2]), "+f"(c[3])
        : "r"(a0), "r"(a1), "r"(a2), "r"(a3), "r"(b0), "r"(b1));
}

// ---------------------------------------------------------------------------
// mma.sync tf32 TN GEMM: C[m][n] = sum_k A[m*K+k] * B[n*K+k] (+ bias[n])
// Block 128x128, BK=32, 8 warps (2x4), warp tile 64x32 (4x4 m16n8k8).
// Padded smem stride (36 floats) -> conflict-free fragment LDS.
// ---------------------------------------------------------------------------
#define BKP 36  // padded K stride in floats

__global__ __launch_bounds__(256) void gemm_mma(
    const float* __restrict__ A, const float* __restrict__ B,
    const float* __restrict__ bias, float* __restrict__ C,
    int N, int K)
{
    __shared__ uint32_t sA[128 * BKP];
    __shared__ uint32_t sB[128 * BKP];

    const int t = threadIdx.x;
    const int wid = t >> 5;
    const int lane = t & 31;
    const int wm = wid >> 2;        // 0..1  (warp row)
    const int wn = wid & 3;         // 0..3  (warp col)
    const int g = lane >> 2;        // groupID 0..7
    const int tg = lane & 3;        // thread-in-group 0..3
    const int bm = blockIdx.y * 128;
    const int bn = blockIdx.x * 128;

    float c[16][4];
#pragma unroll
    for (int i = 0; i < 16; i++)
#pragma unroll
        for (int j = 0; j < 4; j++) c[i][j] = 0.f;

    const int nchunk = K >> 5;      // K/32
    for (int ch = 0; ch < nchunk; ch++) {
        const int kbase = ch << 5;
        __syncthreads();
        // fill: 128 rows x 8 float4 per operand = 1024 float4; 4 per thread
#pragma unroll
        for (int i = 0; i < 4; i++) {
            const int e = i * 256 + t;        // 0..1023
            const int r = e >> 3;             // row 0..127
            const int c4 = e & 7;             // float4 col 0..7
            float4 av = *(const float4*)(A + (size_t)(bm + r) * K + kbase + c4 * 4);
            float4 bv = *(const float4*)(B + (size_t)(bn + r) * K + kbase + c4 * 4);
            uint32_t* pa = &sA[r * BKP + c4 * 4];
            uint32_t* pb = &sB[r * BKP + c4 * 4];
            pa[0] = cvt_tf32(av.x); pa[1] = cvt_tf32(av.y);
            pa[2] = cvt_tf32(av.z); pa[3] = cvt_tf32(av.w);
            pb[0] = cvt_tf32(bv.x); pb[1] = cvt_tf32(bv.y);
            pb[2] = cvt_tf32(bv.z); pb[3] = cvt_tf32(bv.w);
        }
        __syncthreads();

#pragma unroll
        for (int ks = 0; ks < 4; ks++) {
            const int k0 = ks * 8;
            // A fragments: 4 m-tiles
            uint32_t af[4][4];
#pragma unroll
            for (int mt = 0; mt < 4; mt++) {
                const int r0 = wm * 64 + mt * 16;
                af[mt][0] = sA[(r0 + g) * BKP + k0 + tg];
                af[mt][1] = sA[(r0 + g + 8) * BKP + k0 + tg];
                af[mt][2] = sA[(r0 + g) * BKP + k0 + tg + 4];
                af[mt][3] = sA[(r0 + g + 8) * BKP + k0 + tg + 4];
            }
            // B fragments: 4 n-tiles
            uint32_t bf[4][2];
#pragma unroll
            for (int nt = 0; nt < 4; nt++) {
                const int r0 = wn * 32 + nt * 8;
                bf[nt][0] = sB[(r0 + g) * BKP + k0 + tg];
                bf[nt][1] = sB[(r0 + g) * BKP + k0 + tg + 4];
            }
#pragma unroll
            for (int mt = 0; mt < 4; mt++)
#pragma unroll
                for (int nt = 0; nt < 4; nt++)
                    mma_tf32(c[mt * 4 + nt],
                             af[mt][0], af[mt][1], af[mt][2], af[mt][3],
                             bf[nt][0], bf[nt][1]);
        }
    }

    // epilogue: c0,c1 -> (row=g, col=2*tg, 2*tg+1); c2,c3 -> row=g+8
#pragma unroll
    for (int mt = 0; mt < 4; mt++) {
        const int row0 = bm + wm * 64 + mt * 16 + g;
#pragma unroll
        for (int nt = 0; nt < 4; nt++) {
            const int col = bn + wn * 32 + nt * 8 + tg * 2;
            float b0 = 0.f, b1 = 0.f;
            if (bias) { b0 = bias[col]; b1 = bias[col + 1]; }
            float2 v0 = make_float2(c[mt * 4 + nt][0] + b0, c[mt * 4 + nt][1] + b1);
            float2 v1 = make_float2(c[mt * 4 + nt][2] + b0, c[mt * 4 + nt][3] + b1);
            *(float2*)(C + (size_t)row0 * N + col) = v0;
            *(float2*)(C + (size_t)(row0 + 8) * N + col) = v1;
        }
    }
}

// ---------------------------------------------------------------------------
// Flash attention: one thread = one query row. d=32 in registers. (unchanged)
// ---------------------------------------------------------------------------
__global__ __launch_bounds__(128) void attn_kernel(float* __restrict__ out)
{
    const int b = blockIdx.z;
    const int h = blockIdx.y;
    const int t = threadIdx.x;
    const int n = blockIdx.x * 128 + t;
    const float scale = 0.17677669529663689f;  // 1/sqrt(32)

    __shared__ float Ks[32][32];
    __shared__ float Vs[32][32];

    const float* qkv = g_qkv;
    const size_t base = (size_t)b * NTOK * C3;

    float q[32], acc[32];
    {
        const float* qp = qkv + base + (size_t)n * C3 + h * HD;
#pragma unroll
        for (int i = 0; i < 8; i++) {
            float4 v = *(const float4*)(qp + i * 4);
            q[i * 4 + 0] = v.x; q[i * 4 + 1] = v.y;
            q[i * 4 + 2] = v.z; q[i * 4 + 3] = v.w;
        }
    }
#pragma unroll
    for (int i = 0; i < 32; i++) acc[i] = 0.f;

    float mrun = -1e30f, l = 0.f;

    for (int kt = 0; kt < 32; kt++) {
        __syncthreads();
#pragma unroll
        for (int i = 0; i < 2; i++) {
            int idx = t + i * 128;
            int r = idx >> 3;
            int c4 = (idx & 7) << 2;
            const float* kp = qkv + base + (size_t)(kt * 32 + r) * C3 + DIM + h * HD + c4;
            *(float4*)&Ks[r][c4] = *(const float4*)kp;
            *(float4*)&Vs[r][c4] = *(const float4*)(kp + DIM);
        }
        __syncthreads();

        float s[32];
        float tmax = -1e30f;
#pragma unroll
        for (int j = 0; j < 32; j++) {
            float sj = 0.f;
#pragma unroll
            for (int i = 0; i < 8; i++) {
                float4 k4 = *(const float4*)&Ks[j][i * 4];
                sj = fmaf(q[i * 4 + 0], k4.x, sj);
                sj = fmaf(q[i * 4 + 1], k4.y, sj);
                sj = fmaf(q[i * 4 + 2], k4.z, sj);
                sj = fmaf(q[i * 4 + 3], k4.w, sj);
            }
            sj *= scale;
            s[j] = sj;
            tmax = fmaxf(tmax, sj);
        }

        float mnew = fmaxf(mrun, tmax);
        float alpha = __expf(mrun - mnew);
        l *= alpha;
#pragma unroll
        for (int i = 0; i < 32; i++) acc[i] *= alpha;

#pragma unroll
        for (int j = 0; j < 32; j++) {
            float p = __expf(s[j] - mnew);
            l += p;
#pragma unroll
            for (int i = 0; i < 8; i++) {
                float4 v4 = *(const float4*)&Vs[j][i * 4];
                acc[i * 4 + 0] = fmaf(p, v4.x, acc[i * 4 + 0]);
                acc[i * 4 + 1] = fmaf(p, v4.y, acc[i * 4 + 1]);
                acc[i * 4 + 2] = fmaf(p, v4.z, acc[i * 4 + 2]);
                acc[i * 4 + 3] = fmaf(p, v4.w, acc[i * 4 + 3]);
            }
        }
        mrun = mnew;
    }

    float inv = 1.f / l;
    float* op = out + (size_t)(b * NTOK + n) * DIM + h * HD;
#pragma unroll
    for (int i = 0; i < 8; i++) {
        float4 v = make_float4(acc[i * 4 + 0] * inv, acc[i * 4 + 1] * inv,
                               acc[i * 4 + 2] * inv, acc[i * 4 + 3] * inv);
        *(float4*)(op + i * 4) = v;
    }
}

// ---------------------------------------------------------------------------
// LePE 5x5 depthwise conv, added into attention output. (unchanged)
// ---------------------------------------------------------------------------
__global__ __launch_bounds__(512) void lepe_kernel(
    const float* __restrict__ x, const float* __restrict__ w,
    const float* __restrict__ bias, float* __restrict__ out)
{
    const int c = threadIdx.x;
    const int pix = blockIdx.x;
    const int b = pix >> 10;
    const int y = (pix >> 5) & 31;
    const int xx = pix & 31;

    float wreg[25];
#pragma unroll
    for (int i = 0; i < 25; i++) wreg[i] = w[c * 25 + i];

    float acc = bias[c];
#pragma unroll
    for (int dy = 0; dy < 5; dy++) {
        int yy = y + dy - 2;
        if (yy < 0 || yy > 31) continue;
#pragma unroll
        for (int dx = 0; dx < 5; dx++) {
            int xs = xx + dx - 2;
            if (xs < 0 || xs > 31) continue;
            acc = fmaf(x[((size_t)((b * 32 + yy) * 32 + xs)) * DIM + c],
                       wreg[dy * 5 + dx], acc);
        }
    }
    out[(size_t)pix * DIM + c] += acc;
}

// ---------------------------------------------------------------------------
extern "C" void kernel_launch(void* const* d_in, const int* in_sizes, int n_in,
                              void* d_out, int out_size)
{
    const float* x      = (const float*)d_in[0];
    const float* w_qkv  = (const float*)d_in[1];
    const float* w_proj = (const float*)d_in[2];
    const float* b_proj = (const float*)d_in[3];
    const float* w_lepe = (const float*)d_in[4];
    const float* b_lepe = (const float*)d_in[5];
    float* out = (float*)d_out;

    float *qkv_ptr = nullptr, *ao_ptr = nullptr;
    cudaGetSymbolAddress((void**)&qkv_ptr, g_qkv);
    cudaGetSymbolAddress((void**)&ao_ptr, g_ao);

    // 1) qkv = x @ w_qkv^T   [8192,512] x [1536,512]^T  (mma.sync tf32)
    {
        dim3 grid(C3 / 128, M_ROWS / 128);
        gemm_mma<<<grid, 256>>>(x, w_qkv, nullptr, qkv_ptr, C3, DIM);
    }
    // 2) attention -> g_ao
    {
        dim3 grid(NTOK / 128, NHEADS, BATCH);
        attn_kernel<<<grid, 128>>>(ao_ptr);
    }
    // 3) g_ao += lepe(x)
    {
        lepe_kernel<<<BATCH * HH * WW, DIM>>>(x, w_lepe, b_lepe, ao_ptr);
    }
    // 4) out = g_ao @ w_proj^T + b_proj  (mma.sync tf32)
    {
        dim3 grid(DIM / 128, M_ROWS / 128);
        gemm_mma<<<grid, 256>>>(ao_ptr, w_proj, b_proj, out, DIM, DIM);
    }
}

// round 11
// speedup vs baseline: 2.8829x; 2.1346x over previous
#include <cuda_runtime.h>
#include <cuda_bf16.h>
#include <cstdint>
#include <cstddef>

// ---------------------------------------------------------------------------
// AttentionLePE: x[8,32,32,512] -> qkv GEMM -> 16-head attention (d=32)
//                + 5x5 depthwise conv (LePE) -> proj GEMM + bias
// Round 10: attention converted to mma.sync tf32 flash kernel (the scalar
// FFMA attention was ~620us of the 814us total). GEMMs unchanged from R9.
// ---------------------------------------------------------------------------

#define BATCH 8
#define HH 32
#define WW 32
#define DIM 512
#define NHEADS 16
#define HD 32
#define NTOK 1024              // HH*WW
#define M_ROWS (BATCH * NTOK)  // 8192
#define C3 (3 * DIM)           // 1536

__device__ float g_qkv[(size_t)M_ROWS * C3];   // 50.3 MB
__device__ float g_ao[(size_t)M_ROWS * DIM];   // 16.8 MB (attn out + lepe)

__device__ __forceinline__ uint32_t cvt_tf32(float f) {
    uint32_t r;
    asm("cvt.rna.tf32.f32 %0, %1;" : "=r"(r) : "f"(f));
    return r;
}

__device__ __forceinline__ void mma_tf32(
    float c[4], uint32_t a0, uint32_t a1, uint32_t a2, uint32_t a3,
    uint32_t b0, uint32_t b1)
{
    asm volatile(
        "mma.sync.aligned.m16n8k8.row.col.f32.tf32.tf32.f32 "
        "{%0,%1,%2,%3}, {%4,%5,%6,%7}, {%8,%9}, {%0,%1,%2,%3};"
        : "+f"(c[0]), "+f"(c[1]), "+f"(c[2]), "+f"(c[3])
        : "r"(a0), "r"(a1), "r"(a2), "r"(a3), "r"(b0), "r"(b1));
}

// ---------------------------------------------------------------------------
// mma.sync tf32 TN GEMM: C[m][n] = sum_k A[m*K+k] * B[n*K+k] (+ bias[n])
// Block 128x128, BK=32, 8 warps (2x4), warp tile 64x32 (4x4 m16n8k8).
// ---------------------------------------------------------------------------
#define BKP 36  // padded K stride in floats

__global__ __launch_bounds__(256) void gemm_mma(
    const float* __restrict__ A, const float* __restrict__ B,
    const float* __restrict__ bias, float* __restrict__ C,
    int N, int K)
{
    __shared__ uint32_t sA[128 * BKP];
    __shared__ uint32_t sB[128 * BKP];

    const int t = threadIdx.x;
    const int wid = t >> 5;
    const int lane = t & 31;
    const int wm = wid >> 2;        // 0..1  (warp row)
    const int wn = wid & 3;         // 0..3  (warp col)
    const int g = lane >> 2;        // groupID 0..7
    const int tg = lane & 3;        // thread-in-group 0..3
    const int bm = blockIdx.y * 128;
    const int bn = blockIdx.x * 128;

    float c[16][4];
#pragma unroll
    for (int i = 0; i < 16; i++)
#pragma unroll
        for (int j = 0; j < 4; j++) c[i][j] = 0.f;

    const int nchunk = K >> 5;      // K/32
    for (int ch = 0; ch < nchunk; ch++) {
        const int kbase = ch << 5;
        __syncthreads();
#pragma unroll
        for (int i = 0; i < 4; i++) {
            const int e = i * 256 + t;        // 0..1023
            const int r = e >> 3;             // row 0..127
            const int c4 = e & 7;             // float4 col 0..7
            float4 av = *(const float4*)(A + (size_t)(bm + r) * K + kbase + c4 * 4);
            float4 bv = *(const float4*)(B + (size_t)(bn + r) * K + kbase + c4 * 4);
            uint32_t* pa = &sA[r * BKP + c4 * 4];
            uint32_t* pb = &sB[r * BKP + c4 * 4];
            pa[0] = cvt_tf32(av.x); pa[1] = cvt_tf32(av.y);
            pa[2] = cvt_tf32(av.z); pa[3] = cvt_tf32(av.w);
            pb[0] = cvt_tf32(bv.x); pb[1] = cvt_tf32(bv.y);
            pb[2] = cvt_tf32(bv.z); pb[3] = cvt_tf32(bv.w);
        }
        __syncthreads();

#pragma unroll
        for (int ks = 0; ks < 4; ks++) {
            const int k0 = ks * 8;
            uint32_t af[4][4];
#pragma unroll
            for (int mt = 0; mt < 4; mt++) {
                const int r0 = wm * 64 + mt * 16;
                af[mt][0] = sA[(r0 + g) * BKP + k0 + tg];
                af[mt][1] = sA[(r0 + g + 8) * BKP + k0 + tg];
                af[mt][2] = sA[(r0 + g) * BKP + k0 + tg + 4];
                af[mt][3] = sA[(r0 + g + 8) * BKP + k0 + tg + 4];
            }
            uint32_t bf[4][2];
#pragma unroll
            for (int nt = 0; nt < 4; nt++) {
                const int r0 = wn * 32 + nt * 8;
                bf[nt][0] = sB[(r0 + g) * BKP + k0 + tg];
                bf[nt][1] = sB[(r0 + g) * BKP + k0 + tg + 4];
            }
#pragma unroll
            for (int mt = 0; mt < 4; mt++)
#pragma unroll
                for (int nt = 0; nt < 4; nt++)
                    mma_tf32(c[mt * 4 + nt],
                             af[mt][0], af[mt][1], af[mt][2], af[mt][3],
                             bf[nt][0], bf[nt][1]);
        }
    }

#pragma unroll
    for (int mt = 0; mt < 4; mt++) {
        const int row0 = bm + wm * 64 + mt * 16 + g;
#pragma unroll
        for (int nt = 0; nt < 4; nt++) {
            const int col = bn + wn * 32 + nt * 8 + tg * 2;
            float b0 = 0.f, b1 = 0.f;
            if (bias) { b0 = bias[col]; b1 = bias[col + 1]; }
            float2 v0 = make_float2(c[mt * 4 + nt][0] + b0, c[mt * 4 + nt][1] + b1);
            float2 v1 = make_float2(c[mt * 4 + nt][2] + b0, c[mt * 4 + nt][3] + b1);
            *(float2*)(C + (size_t)row0 * N + col) = v0;
            *(float2*)(C + (size_t)(row0 + 8) * N + col) = v1;
        }
    }
}

// ---------------------------------------------------------------------------
// Flash attention on mma.sync tf32.
// grid (8 qtiles, 16 heads, 8 batch), 128 threads (4 warps).
// Each warp owns 32 q-rows; K/V tiles of 32 rows; online softmax in
// C-fragment layout; P routed through per-warp smem (stride 36 -> the
// A-fragment read pattern 4g+tg is bank-conflict-free).
// ---------------------------------------------------------------------------
__global__ __launch_bounds__(128) void attn_mma(float* __restrict__ out)
{
    // phase A: Q staging 128x36 floats (4608 u32)
    // phase B: sK 32x36 | sV 32x36 | sP 4 x 32x36  (6912 u32 = 27.6 KB)
    __shared__ uint32_t sm[6912];
    float* smf = (float*)sm;

    const int b = blockIdx.z;
    const int h = blockIdx.y;
    const int qt = blockIdx.x;
    const int t = threadIdx.x;
    const int w = t >> 5;
    const int lane = t & 31;
    const int g = lane >> 2;
    const int tg = lane & 3;
    const float scale = 0.17677669529663689f;  // 1/sqrt(32)
    const size_t base = (size_t)b * NTOK * C3;

    // ---- phase A: stage Q tile, build scaled tf32 A-fragments ----
#pragma unroll
    for (int i = 0; i < 8; i++) {
        const int e = i * 128 + t;        // 0..1023
        const int r = e >> 3;
        const int c4 = e & 7;
        float4 v = *(const float4*)(g_qkv + base + (size_t)(qt * 128 + r) * C3
                                    + h * HD + c4 * 4);
        float* p = smf + r * 36 + c4 * 4;
        p[0] = v.x; p[1] = v.y; p[2] = v.z; p[3] = v.w;
    }
    __syncthreads();

    uint32_t aq[2][4][4];
#pragma unroll
    for (int mt = 0; mt < 2; mt++) {
        const int r0 = w * 32 + mt * 16;
#pragma unroll
        for (int ks = 0; ks < 4; ks++) {
            aq[mt][ks][0] = cvt_tf32(smf[(r0 + g) * 36 + ks * 8 + tg] * scale);
            aq[mt][ks][1] = cvt_tf32(smf[(r0 + g + 8) * 36 + ks * 8 + tg] * scale);
            aq[mt][ks][2] = cvt_tf32(smf[(r0 + g) * 36 + ks * 8 + tg + 4] * scale);
            aq[mt][ks][3] = cvt_tf32(smf[(r0 + g + 8) * 36 + ks * 8 + tg + 4] * scale);
        }
    }

    uint32_t* sK = sm;
    uint32_t* sV = sm + 1152;
    uint32_t* sP = sm + 2304 + w * 1152;

    float o[2][4][4];
#pragma unroll
    for (int mt = 0; mt < 2; mt++)
#pragma unroll
        for (int on = 0; on < 4; on++)
#pragma unroll
            for (int j = 0; j < 4; j++) o[mt][on][j] = 0.f;
    float mrow[2][2] = {{-1e30f, -1e30f}, {-1e30f, -1e30f}};
    float lrow[2][2] = {{0.f, 0.f}, {0.f, 0.f}};

    for (int kt = 0; kt < 32; kt++) {
        __syncthreads();   // protects sK/sV (and phase-A smem on first iter)
        // ---- load K,V tile (32 rows x 32 d), convert to tf32 ----
#pragma unroll
        for (int i = 0; i < 2; i++) {
            const int e = i * 128 + t;    // 0..255
            const int r = e >> 3;
            const int c4 = e & 7;
            const float* kp = g_qkv + base + (size_t)(kt * 32 + r) * C3
                              + DIM + h * HD + c4 * 4;
            float4 kv = *(const float4*)kp;
            float4 vv = *(const float4*)(kp + DIM);
            uint32_t* pk = sK + r * 36 + c4 * 4;
            uint32_t* pv = sV + r * 36 + c4 * 4;
            pk[0] = cvt_tf32(kv.x); pk[1] = cvt_tf32(kv.y);
            pk[2] = cvt_tf32(kv.z); pk[3] = cvt_tf32(kv.w);
            pv[0] = cvt_tf32(vv.x); pv[1] = cvt_tf32(vv.y);
            pv[2] = cvt_tf32(vv.z); pv[3] = cvt_tf32(vv.w);
        }
        __syncthreads();

        // ---- S = (Q*scale) K^T ----
        float s[2][4][4];
#pragma unroll
        for (int mt = 0; mt < 2; mt++)
#pragma unroll
            for (int nt = 0; nt < 4; nt++)
#pragma unroll
                for (int j = 0; j < 4; j++) s[mt][nt][j] = 0.f;

#pragma unroll
        for (int ks = 0; ks < 4; ks++) {
            uint32_t bk[4][2];
#pragma unroll
            for (int nt = 0; nt < 4; nt++) {
                bk[nt][0] = sK[(nt * 8 + g) * 36 + ks * 8 + tg];
                bk[nt][1] = sK[(nt * 8 + g) * 36 + ks * 8 + tg + 4];
            }
#pragma unroll
            for (int mt = 0; mt < 2; mt++)
#pragma unroll
                for (int nt = 0; nt < 4; nt++)
                    mma_tf32(s[mt][nt],
                             aq[mt][ks][0], aq[mt][ks][1],
                             aq[mt][ks][2], aq[mt][ks][3],
                             bk[nt][0], bk[nt][1]);
        }

        // ---- online softmax (per row-slot) ----
#pragma unroll
        for (int mt = 0; mt < 2; mt++) {
#pragma unroll
            for (int ri = 0; ri < 2; ri++) {
                float tmax = -1e30f;
#pragma unroll
                for (int nt = 0; nt < 4; nt++)
                    tmax = fmaxf(tmax, fmaxf(s[mt][nt][ri * 2], s[mt][nt][ri * 2 + 1]));
                tmax = fmaxf(tmax, __shfl_xor_sync(0xffffffffu, tmax, 1));
                tmax = fmaxf(tmax, __shfl_xor_sync(0xffffffffu, tmax, 2));
                const float mold = mrow[mt][ri];
                const float mnew = fmaxf(mold, tmax);
                const float alpha = __expf(mold - mnew);
                mrow[mt][ri] = mnew;
                float lsum = 0.f;
#pragma unroll
                for (int nt = 0; nt < 4; nt++) {
                    float p0 = __expf(s[mt][nt][ri * 2] - mnew);
                    float p1 = __expf(s[mt][nt][ri * 2 + 1] - mnew);
                    s[mt][nt][ri * 2] = p0;
                    s[mt][nt][ri * 2 + 1] = p1;
                    lsum += p0 + p1;
                }
                lrow[mt][ri] = lrow[mt][ri] * alpha + lsum;
#pragma unroll
                for (int on = 0; on < 4; on++) {
                    o[mt][on][ri * 2] *= alpha;
                    o[mt][on][ri * 2 + 1] *= alpha;
                }
            }
        }

        // ---- P -> per-warp smem (tf32), layout for A-fragment reads ----
#pragma unroll
        for (int mt = 0; mt < 2; mt++)
#pragma unroll
            for (int ri = 0; ri < 2; ri++) {
                const int row = mt * 16 + ri * 8 + g;
#pragma unroll
                for (int nt = 0; nt < 4; nt++) {
                    uint32_t* p = sP + row * 36 + nt * 8 + tg * 2;
                    p[0] = cvt_tf32(s[mt][nt][ri * 2]);
                    p[1] = cvt_tf32(s[mt][nt][ri * 2 + 1]);
                }
            }
        __syncwarp();

        // ---- O += P V ----
#pragma unroll
        for (int ks = 0; ks < 4; ks++) {
            uint32_t ap[2][4];
#pragma unroll
            for (int mt = 0; mt < 2; mt++) {
                ap[mt][0] = sP[(mt * 16 + g) * 36 + ks * 8 + tg];
                ap[mt][1] = sP[(mt * 16 + 8 + g) * 36 + ks * 8 + tg];
                ap[mt][2] = sP[(mt * 16 + g) * 36 + ks * 8 + tg + 4];
                ap[mt][3] = sP[(mt * 16 + 8 + g) * 36 + ks * 8 + tg + 4];
            }
            uint32_t bv[4][2];
#pragma unroll
            for (int on = 0; on < 4; on++) {
                bv[on][0] = sV[(ks * 8 + tg) * 36 + on * 8 + g];
                bv[on][1] = sV[(ks * 8 + tg + 4) * 36 + on * 8 + g];
            }
#pragma unroll
            for (int mt = 0; mt < 2; mt++)
#pragma unroll
                for (int on = 0; on < 4; on++)
                    mma_tf32(o[mt][on],
                             ap[mt][0], ap[mt][1], ap[mt][2], ap[mt][3],
                             bv[on][0], bv[on][1]);
        }
        __syncwarp();
    }

    // ---- epilogue: normalize and store ----
#pragma unroll
    for (int mt = 0; mt < 2; mt++)
#pragma unroll
        for (int ri = 0; ri < 2; ri++) {
            float l = lrow[mt][ri];
            l += __shfl_xor_sync(0xffffffffu, l, 1);
            l += __shfl_xor_sync(0xffffffffu, l, 2);
            const float inv = 1.f / l;
            const int qrow = qt * 128 + w * 32 + mt * 16 + ri * 8 + g;
            float* op = out + (size_t)(b * NTOK + qrow) * DIM + h * HD;
#pragma unroll
            for (int on = 0; on < 4; on++) {
                float2 v = make_float2(o[mt][on][ri * 2] * inv,
                                       o[mt][on][ri * 2 + 1] * inv);
                *(float2*)(op + on * 8 + tg * 2) = v;
            }
        }
}

// ---------------------------------------------------------------------------
// LePE 5x5 depthwise conv, added into attention output. (unchanged)
// ---------------------------------------------------------------------------
__global__ __launch_bounds__(512) void lepe_kernel(
    const float* __restrict__ x, const float* __restrict__ w,
    const float* __restrict__ bias, float* __restrict__ out)
{
    const int c = threadIdx.x;
    const int pix = blockIdx.x;
    const int b = pix >> 10;
    const int y = (pix >> 5) & 31;
    const int xx = pix & 31;

    float wreg[25];
#pragma unroll
    for (int i = 0; i < 25; i++) wreg[i] = w[c * 25 + i];

    float acc = bias[c];
#pragma unroll
    for (int dy = 0; dy < 5; dy++) {
        int yy = y + dy - 2;
        if (yy < 0 || yy > 31) continue;
#pragma unroll
        for (int dx = 0; dx < 5; dx++) {
            int xs = xx + dx - 2;
            if (xs < 0 || xs > 31) continue;
            acc = fmaf(x[((size_t)((b * 32 + yy) * 32 + xs)) * DIM + c],
                       wreg[dy * 5 + dx], acc);
        }
    }
    out[(size_t)pix * DIM + c] += acc;
}

// ---------------------------------------------------------------------------
extern "C" void kernel_launch(void* const* d_in, const int* in_sizes, int n_in,
                              void* d_out, int out_size)
{
    const float* x      = (const float*)d_in[0];
    const float* w_qkv  = (const float*)d_in[1];
    const float* w_proj = (const float*)d_in[2];
    const float* b_proj = (const float*)d_in[3];
    const float* w_lepe = (const float*)d_in[4];
    const float* b_lepe = (const float*)d_in[5];
    float* out = (float*)d_out;

    float *qkv_ptr = nullptr, *ao_ptr = nullptr;
    cudaGetSymbolAddress((void**)&qkv_ptr, g_qkv);
    cudaGetSymbolAddress((void**)&ao_ptr, g_ao);

    // 1) qkv = x @ w_qkv^T  (mma.sync tf32)
    {
        dim3 grid(C3 / 128, M_ROWS / 128);
        gemm_mma<<<grid, 256>>>(x, w_qkv, nullptr, qkv_ptr, C3, DIM);
    }
    // 2) attention -> g_ao  (mma.sync tf32 flash)
    {
        dim3 grid(NTOK / 128, NHEADS, BATCH);
        attn_mma<<<grid, 128>>>(ao_ptr);
    }
    // 3) g_ao += lepe(x)
    {
        lepe_kernel<<<BATCH * HH * WW, DIM>>>(x, w_lepe, b_lepe, ao_ptr);
    }
    // 4) out = g_ao @ w_proj^T + b_proj  (mma.sync tf32)
    {
        dim3 grid(DIM / 128, M_ROWS / 128);
        gemm_mma<<<grid, 256>>>(ao_ptr, w_proj, b_proj, out, DIM, DIM);
    }
}